// round 11
// baseline (speedup 1.0000x reference)
#include <cuda_runtime.h>
#include <cuda_bf16.h>
#include <cstdint>
#include <cstddef>

#define B 8
#define L 1024
#define H 16
#define DK 64
#define DM 1024
#define BH (B*H)

// ---------------- scratch ----------------------------------------------------
__device__ float g_preln[(size_t)B * L * DM];
__device__ int   g_mask_u8;

__device__ __nv_bfloat16 g_Xh[(size_t)B * L * DM];
__device__ __nv_bfloat16 g_Xl[(size_t)B * L * DM];
__device__ __nv_bfloat16 g_Wh[4][(size_t)DM * DM];   // q,k,v,o
__device__ __nv_bfloat16 g_Wl[4][(size_t)DM * DM];
__device__ __nv_bfloat16 g_Qh[(size_t)BH * L * DK];  // pre-scaled by 0.125
__device__ __nv_bfloat16 g_Ql[(size_t)BH * L * DK];
__device__ __nv_bfloat16 g_Kh[(size_t)BH * L * DK];
__device__ __nv_bfloat16 g_Kl[(size_t)BH * L * DK];
__device__ __nv_bfloat16 g_Vh[(size_t)BH * L * DK];
__device__ __nv_bfloat16 g_Vl[(size_t)BH * L * DK];
__device__ __nv_bfloat16 g_Ch[(size_t)B * L * DM];
__device__ __nv_bfloat16 g_Cl[(size_t)B * L * DM];

__device__ __forceinline__ uint32_t smem_u32(const void* p) {
    return (uint32_t)__cvta_generic_to_shared(p);
}

#define MMA_STEP(afr, bfr, accp)                                              \
    asm volatile(                                                              \
        "mma.sync.aligned.m16n8k16.row.col.f32.bf16.bf16.f32 "                 \
        "{%0,%1,%2,%3},{%4,%5,%6,%7},{%8,%9},{%0,%1,%2,%3};"                   \
        : "+f"((accp)[0]), "+f"((accp)[1]), "+f"((accp)[2]), "+f"((accp)[3])   \
        : "r"((afr)[0]), "r"((afr)[1]), "r"((afr)[2]), "r"((afr)[3]),          \
          "r"((bfr)[0]), "r"((bfr)[1]))

#define LDSM_X4(frag, ad)                                                      \
    asm volatile("ldmatrix.sync.aligned.m8n8.x4.shared.b16 {%0,%1,%2,%3},[%4];"\
        : "=r"((frag)[0]), "=r"((frag)[1]), "=r"((frag)[2]), "=r"((frag)[3])   \
        : "r"(ad))

#define LDSM_X2(frag, ad)                                                      \
    asm volatile("ldmatrix.sync.aligned.m8n8.x2.shared.b16 {%0,%1},[%2];"      \
        : "=r"((frag)[0]), "=r"((frag)[1]) : "r"(ad))

#define LDSM_X2T(frag, ad)                                                     \
    asm volatile("ldmatrix.sync.aligned.m8n8.x2.trans.shared.b16 {%0,%1},[%2];"\
        : "=r"((frag)[0]), "=r"((frag)[1]) : "r"(ad))

__device__ __forceinline__ void cp16(uint32_t saddr, const void* g) {
    asm volatile("cp.async.ca.shared.global [%0], [%1], 16;" :: "r"(saddr), "l"(g));
}
#define CP_COMMIT()  asm volatile("cp.async.commit_group;" ::: "memory")
#define CP_WAIT0()   asm volatile("cp.async.wait_group 0;" ::: "memory")

// ---------------- mask dtype detection --------------------------------------
__global__ void detect_mask_kernel(const unsigned int* __restrict__ m)
{
    __shared__ int s_any;
    if (threadIdx.x == 0) s_any = 0;
    __syncthreads();
    int any = 0;
    for (int i = threadIdx.x; i < 16384; i += 256)
        if (m[i] > 1u) any = 1;
    if (any) atomicOr(&s_any, 1);
    __syncthreads();
    if (threadIdx.x == 0) g_mask_u8 = s_any;
}

// ---------------- fp32 -> bf16 hi/lo split ----------------------------------
__global__ __launch_bounds__(256) void cvt_split_kernel(
    const float4* __restrict__ in, __nv_bfloat16* __restrict__ h,
    __nv_bfloat16* __restrict__ l, int n4)
{
    int i = blockIdx.x * 256 + threadIdx.x;
    if (i >= n4) return;
    float4 v = in[i];
    __nv_bfloat16 h0 = __float2bfloat16(v.x);
    __nv_bfloat16 h1 = __float2bfloat16(v.y);
    __nv_bfloat16 h2 = __float2bfloat16(v.z);
    __nv_bfloat16 h3 = __float2bfloat16(v.w);
    __nv_bfloat162* hp = (__nv_bfloat162*)(h + (size_t)i * 4);
    hp[0] = __nv_bfloat162(h0, h1);
    hp[1] = __nv_bfloat162(h2, h3);
    __nv_bfloat162* lp = (__nv_bfloat162*)(l + (size_t)i * 4);
    lp[0] = __nv_bfloat162(__float2bfloat16(v.x - __bfloat162float(h0)),
                           __float2bfloat16(v.y - __bfloat162float(h1)));
    lp[1] = __nv_bfloat162(__float2bfloat16(v.z - __bfloat162float(h2)),
                           __float2bfloat16(v.w - __bfloat162float(h3)));
}

// ---------------- mma.sync bf16 split GEMM core (cp.async pipelined) ---------
#define GEMM_MAIN(AH, AL, BH_, BL_)                                            \
    __shared__ __nv_bfloat16 sA[2][128][40];                                   \
    __shared__ __nv_bfloat16 sB[2][32][136];                                   \
    const int tid = threadIdx.x, lane = tid & 31, warp = tid >> 5;             \
    const int wm = warp >> 2, wn = warp & 3;                                   \
    const int row0 = blockIdx.y * 128, col0 = blockIdx.x * 128;                \
    float acc[4][4][4];                                                        \
    _Pragma("unroll") for (int i = 0; i < 4; i++)                              \
    _Pragma("unroll") for (int j = 0; j < 4; j++)                              \
    _Pragma("unroll") for (int f = 0; f < 4; f++) acc[i][j][f] = 0.f;          \
    const int ar = tid >> 1, ac = (tid & 1) * 16;                              \
    const int br = tid >> 3, bc = (tid & 7) * 8;                               \
    auto ld_chunk = [&](int cc, int bu) {                                      \
        int ph = cc >> 5, k0 = (cc & 31) * 32;                                 \
        const __nv_bfloat16* Ap = (ph == 1) ? AL : AH;                         \
        const __nv_bfloat16* Bp = (ph == 2) ? BL_ : BH_;                       \
        cp16(smem_u32(&sA[bu][ar][ac]),                                        \
             Ap + (size_t)(row0 + ar) * DM + k0 + ac);                         \
        cp16(smem_u32(&sA[bu][ar][ac + 8]),                                    \
             Ap + (size_t)(row0 + ar) * DM + k0 + ac + 8);                     \
        cp16(smem_u32(&sB[bu][br][bc]),                                        \
             Bp + (size_t)(k0 + br) * DM + col0 + bc);                         \
        cp16(smem_u32(&sB[bu][br][bc + 64]),                                   \
             Bp + (size_t)(k0 + br) * DM + col0 + bc + 64);                    \
        CP_COMMIT();                                                           \
    };                                                                         \
    ld_chunk(0, 0);                                                            \
    CP_WAIT0();                                                                \
    __syncthreads();                                                           \
    int buf = 0;                                                               \
    for (int cc = 0; cc < 96; cc++) {                                          \
        const bool nxt = (cc + 1) < 96;                                        \
        if (nxt) ld_chunk(cc + 1, buf ^ 1);                                    \
        _Pragma("unroll")                                                      \
        for (int ks = 0; ks < 32; ks += 16) {                                  \
            uint32_t afr[4][4], bfr[4][2];                                     \
            _Pragma("unroll")                                                  \
            for (int i = 0; i < 4; i++) {                                      \
                uint32_t ad = smem_u32(                                        \
                    &sA[buf][wm * 64 + i * 16 + (lane & 15)]                   \
                        [ks + (lane >> 4) * 8]);                               \
                LDSM_X4(afr[i], ad);                                           \
            }                                                                  \
            _Pragma("unroll")                                                  \
            for (int j = 0; j < 4; j++) {                                      \
                uint32_t bd = smem_u32(                                        \
                    &sB[buf][ks + (lane & 15)][wn * 32 + j * 8]);              \
                LDSM_X2T(bfr[j], bd);                                          \
            }                                                                  \
            _Pragma("unroll")                                                  \
            for (int i = 0; i < 4; i++)                                        \
            _Pragma("unroll")                                                  \
            for (int j = 0; j < 4; j++) MMA_STEP(afr[i], bfr[j], acc[i][j]);   \
        }                                                                      \
        if (nxt) CP_WAIT0();                                                   \
        __syncthreads();                                                       \
        buf ^= 1;                                                              \
    }

// QKV: writes bf16 hi/lo splits directly (Q pre-scaled by 0.125)
__global__ __launch_bounds__(256) void qkv_mma_kernel()
{
    const int z = blockIdx.z;
    const __nv_bfloat16* BHp = g_Wh[z];
    const __nv_bfloat16* BLp = g_Wl[z];

    GEMM_MAIN(g_Xh, g_Xl, BHp, BLp)

    __nv_bfloat16* Oh = (z == 0) ? g_Qh : (z == 1) ? g_Kh : g_Vh;
    __nv_bfloat16* Ol = (z == 0) ? g_Ql : (z == 1) ? g_Kl : g_Vl;
    const float sc = (z == 0) ? 0.125f : 1.0f;

    const int lr = lane >> 2, lc = (lane & 3) * 2;
#pragma unroll
    for (int i = 0; i < 4; i++) {
        int r0 = row0 + wm * 64 + i * 16 + lr;
#pragma unroll
        for (int j = 0; j < 4; j++) {
            int c = col0 + wn * 32 + j * 8 + lc;
            int h_ = c >> 6, d_ = c & 63;
#pragma unroll
            for (int hrow = 0; hrow < 2; hrow++) {
                int r = r0 + hrow * 8;
                int b_ = r >> 10, l_ = r & 1023;
                float v0 = acc[i][j][hrow * 2 + 0] * sc;
                float v1 = acc[i][j][hrow * 2 + 1] * sc;
                __nv_bfloat16 h0 = __float2bfloat16(v0);
                __nv_bfloat16 h1 = __float2bfloat16(v1);
                size_t off = (((size_t)(b_ * H + h_)) * L + l_) * DK + d_;
                *(__nv_bfloat162*)(Oh + off) = __nv_bfloat162(h0, h1);
                *(__nv_bfloat162*)(Ol + off) = __nv_bfloat162(
                    __float2bfloat16(v0 - __bfloat162float(h0)),
                    __float2bfloat16(v1 - __bfloat162float(h1)));
            }
        }
    }
}

__global__ __launch_bounds__(256) void oproj_mma_kernel(const float* __restrict__ X)
{
    GEMM_MAIN(g_Ch, g_Cl, g_Wh[3], g_Wl[3])

    const int lr = lane >> 2, lc = (lane & 3) * 2;
#pragma unroll
    for (int i = 0; i < 4; i++) {
        int r0 = row0 + wm * 64 + i * 16 + lr;
#pragma unroll
        for (int j = 0; j < 4; j++) {
            int c = col0 + wn * 32 + j * 8 + lc;
#pragma unroll
            for (int hrow = 0; hrow < 2; hrow++) {
                int r = r0 + hrow * 8;
                float2 xv = *(const float2*)&X[(size_t)r * DM + c];
                float2 o;
                o.x = acc[i][j][hrow * 2 + 0] + xv.x;
                o.y = acc[i][j][hrow * 2 + 1] + xv.y;
                *(float2*)&g_preln[(size_t)r * DM + c] = o;
            }
        }
    }
}

// ---------------- tensor-core attention (128-key chunks, cp.async) -----------
// Block = (bh, 32 q rows), 256 thr / 8 warps (wm 2 x wn 4).
// smem: S[32][1028] f32 | KV 2 bufs x (hi[128][72] + lo[128][72]) | P 1 buf
// Q is staged in the P region (frags built before P is needed).
#define SOFF_KV  131584
#define KVBUF    36864
#define SOFF_P   205312
#define ATTN_SMEM 222720

__global__ __launch_bounds__(256) void attn_mma_kernel(
    const void* __restrict__ mask, float* __restrict__ attn_out)
{
    extern __shared__ char smx[];
    float* S = (float*)smx;

    const int tid = threadIdx.x, lane = tid & 31, warp = tid >> 5;
    const int wm = warp >> 2, wn = warp & 3;
    const int bh = blockIdx.y, b_ = bh >> 4, q0 = blockIdx.x * 32;
    const int u8 = g_mask_u8;
    const uint32_t sb = smem_u32(smx);

    // async load of a 128-row KV chunk (hi+lo), 8 cp16 per thread
    auto load_kv = [&](const __nv_bfloat16* Gh, const __nv_bfloat16* Gl,
                       int kc, int bu) {
        uint32_t base = sb + SOFF_KV + bu * KVBUF;
#pragma unroll
        for (int i = 0; i < 4; i++) {
            int idx = i * 256 + tid;
            int r = idx >> 3, cb = idx & 7;
            cp16(base + r * 144 + cb * 16,
                 Gh + ((size_t)bh * L + kc + r) * DK + cb * 8);
            cp16(base + 18432 + r * 144 + cb * 16,
                 Gl + ((size_t)bh * L + kc + r) * DK + cb * 8);
        }
        CP_COMMIT();
    };

    // ---- stage Q in P region, issue K chunk 0 ----
    {
        __nv_bfloat16* Qsh = (__nv_bfloat16*)(smx + SOFF_P);
        __nv_bfloat16* Qsl = Qsh + 2304;
        int r = tid >> 3, d0 = (tid & 7) * 8;
        *(uint4*)(Qsh + r * 72 + d0) =
            *(const uint4*)(g_Qh + ((size_t)bh * L + q0 + r) * DK + d0);
        *(uint4*)(Qsl + r * 72 + d0) =
            *(const uint4*)(g_Ql + ((size_t)bh * L + q0 + r) * DK + d0);
    }
    load_kv(g_Kh, g_Kl, 0, 0);
    __syncthreads();

    uint32_t qfh[4][4], qfl[4][4];
    {
        const __nv_bfloat16* Qsh = (const __nv_bfloat16*)(smx + SOFF_P);
        const __nv_bfloat16* Qsl = Qsh + 2304;
#pragma unroll
        for (int kk = 0; kk < 4; kk++) {
            uint32_t ad = smem_u32(Qsh + (wm * 16 + (lane & 15)) * 72 +
                                   kk * 16 + (lane >> 4) * 8);
            LDSM_X4(qfh[kk], ad);
            ad = smem_u32(Qsl + (wm * 16 + (lane & 15)) * 72 +
                          kk * 16 + (lane >> 4) * 8);
            LDSM_X4(qfl[kk], ad);
        }
    }

    const int rowA = wm * 16 + (lane >> 2);      // S row for acc[t][0..1]
    const size_t mbA = ((size_t)b_ * L + q0 + rowA) * L;
    const size_t mbB = mbA + 8 * (size_t)L;

    // ---- score phase: 8 chunks of 128 keys ----
    for (int c = 0; c < 8; c++) {
        int bu = c & 1;
        CP_WAIT0();
        __syncthreads();
        if (c + 1 < 8) load_kv(g_Kh, g_Kl, (c + 1) * 128, bu ^ 1);
        else           load_kv(g_Vh, g_Vl, 0, bu ^ 1);   // V0 hidden under softmax

        // mask prefetch for this warp's 4 column groups (hidden under MMAs)
        uint32_t mk[4];
        {
            int kc = c * 128;
#pragma unroll
            for (int t = 0; t < 4; t++) {
                int col = kc + wn * 32 + t * 8 + 2 * (lane & 3);
                if (u8) {
                    const unsigned char* m8 = (const unsigned char*)mask;
                    uchar2 a = *(const uchar2*)(m8 + mbA + col);
                    uchar2 bq = *(const uchar2*)(m8 + mbB + col);
                    mk[t] = (a.x ? 1u : 0u) | (a.y ? 2u : 0u) |
                            (bq.x ? 4u : 0u) | (bq.y ? 8u : 0u);
                } else {
                    const int* m32 = (const int*)mask;
                    int2 a = *(const int2*)(m32 + mbA + col);
                    int2 bq = *(const int2*)(m32 + mbB + col);
                    mk[t] = (a.x ? 1u : 0u) | (a.y ? 2u : 0u) |
                            (bq.x ? 4u : 0u) | (bq.y ? 8u : 0u);
                }
            }
        }

        const __nv_bfloat16* KBh = (const __nv_bfloat16*)(smx + SOFF_KV + bu * KVBUF);
        const __nv_bfloat16* KBl = KBh + 9216;

        float acc[4][4];
#pragma unroll
        for (int t = 0; t < 4; t++)
#pragma unroll
            for (int f = 0; f < 4; f++) acc[t][f] = 0.f;

#pragma unroll
        for (int kk = 0; kk < 4; kk++) {
            uint32_t bfh[4][2], bfl[4][2];
#pragma unroll
            for (int t = 0; t < 4; t++) {
                int kb = wn * 32 + t * 8;
                uint32_t ad = smem_u32(KBh + (kb + (lane & 7)) * 72 +
                                       kk * 16 + ((lane >> 3) & 1) * 8);
                LDSM_X2(bfh[t], ad);
                ad = smem_u32(KBl + (kb + (lane & 7)) * 72 +
                              kk * 16 + ((lane >> 3) & 1) * 8);
                LDSM_X2(bfl[t], ad);
            }
#pragma unroll
            for (int t = 0; t < 4; t++) MMA_STEP(qfh[kk], bfh[t], acc[t]);
#pragma unroll
            for (int t = 0; t < 4; t++) MMA_STEP(qfl[kk], bfh[t], acc[t]);
#pragma unroll
            for (int t = 0; t < 4; t++) MMA_STEP(qfh[kk], bfl[t], acc[t]);
        }

#pragma unroll
        for (int t = 0; t < 4; t++) {
            int col = c * 128 + wn * 32 + t * 8 + 2 * (lane & 3);
            float2 vA, vB;
            vA.x = (mk[t] & 1u) ? -1e9f : acc[t][0];
            vA.y = (mk[t] & 2u) ? -1e9f : acc[t][1];
            vB.x = (mk[t] & 4u) ? -1e9f : acc[t][2];
            vB.y = (mk[t] & 8u) ? -1e9f : acc[t][3];
            *(float2*)&S[rowA * 1028 + col] = vA;
            *(float2*)&S[(rowA + 8) * 1028 + col] = vB;
        }
    }
    __syncthreads();

    // ---- softmax + normalize + attn_out: float4, smem-only max -------------
    {
        const int row = tid >> 3, c0 = tid & 7;
        float* Sr = S + row * 1028;

        float mx = -3.4e38f;
#pragma unroll 8
        for (int k = 0; k < 32; k++) {
            int c = (c0 + 8 * k) * 4;
            float4 v = *(float4*)&Sr[c];
            mx = fmaxf(mx, fmaxf(fmaxf(v.x, v.y), fmaxf(v.z, v.w)));
        }
#pragma unroll
        for (int off = 4; off; off >>= 1)
            mx = fmaxf(mx, __shfl_xor_sync(0xffffffffu, mx, off));

        float sum = 0.f;
#pragma unroll 4
        for (int k = 0; k < 32; k++) {
            int c = (c0 + 8 * k) * 4;
            float4 v = *(float4*)&Sr[c];
            v.x = __expf(v.x - mx);
            v.y = __expf(v.y - mx);
            v.z = __expf(v.z - mx);
            v.w = __expf(v.w - mx);
            *(float4*)&Sr[c] = v;
            sum += v.x + v.y + v.z + v.w;
        }
#pragma unroll
        for (int off = 4; off; off >>= 1)
            sum += __shfl_xor_sync(0xffffffffu, sum, off);
        float inv = 1.f / sum;

        float* Ar = attn_out ? (attn_out + ((size_t)bh * L + q0 + row) * L) : nullptr;
#pragma unroll 4
        for (int k = 0; k < 32; k++) {
            int c = (c0 + 8 * k) * 4;
            float4 v = *(float4*)&Sr[c];
            v.x *= inv; v.y *= inv; v.z *= inv; v.w *= inv;
            *(float4*)&Sr[c] = v;
            if (Ar) *(float4*)&Ar[c] = v;
        }
    }

    // convert P chunk (128 cols at kc) into the single P buffer
    auto convP = [&](int kc) {
        __nv_bfloat16* Ph = (__nv_bfloat16*)(smx + SOFF_P);
        __nv_bfloat16* Pl = Ph + 32 * 136;
        int r = tid >> 3, cb = (tid & 7) * 16;
        const float* Sr = S + r * 1028 + kc + cb;
#pragma unroll
        for (int i = 0; i < 16; i += 4) {
            float4 p = *(const float4*)&Sr[i];
            __nv_bfloat16 h0 = __float2bfloat16(p.x);
            __nv_bfloat16 h1 = __float2bfloat16(p.y);
            __nv_bfloat16 h2 = __float2bfloat16(p.z);
            __nv_bfloat16 h3 = __float2bfloat16(p.w);
            __nv_bfloat162* php = (__nv_bfloat162*)(Ph + r * 136 + cb + i);
            php[0] = __nv_bfloat162(h0, h1);
            php[1] = __nv_bfloat162(h2, h3);
            __nv_bfloat162* plp = (__nv_bfloat162*)(Pl + r * 136 + cb + i);
            plp[0] = __nv_bfloat162(
                __float2bfloat16(p.x - __bfloat162float(h0)),
                __float2bfloat16(p.y - __bfloat162float(h1)));
            plp[1] = __nv_bfloat162(
                __float2bfloat16(p.z - __bfloat162float(h2)),
                __float2bfloat16(p.w - __bfloat162float(h3)));
        }
    };

    // ---- context phase: 8 chunks of 128 keys ----
    float cacc[2][4];
#pragma unroll
    for (int t = 0; t < 2; t++)
#pragma unroll
        for (int f = 0; f < 4; f++) cacc[t][f] = 0.f;

    for (int c = 0; c < 8; c++) {
        int bu = c & 1;
        CP_WAIT0();
        __syncthreads();                 // V(c) ready; P free; S final
        convP(c * 128);
        if (c + 1 < 8) load_kv(g_Vh, g_Vl, (c + 1) * 128, bu ^ 1);
        __syncthreads();                 // P ready

        const __nv_bfloat16* VBh = (const __nv_bfloat16*)(smx + SOFF_KV + bu * KVBUF);
        const __nv_bfloat16* VBl = VBh + 9216;
        const __nv_bfloat16* Ph = (const __nv_bfloat16*)(smx + SOFF_P);
        const __nv_bfloat16* Pl = Ph + 32 * 136;

#pragma unroll
        for (int kk = 0; kk < 8; kk++) {
            uint32_t pah[4], pal[4], bvh[2][2], bvl[2][2];
            uint32_t ad = smem_u32(Ph + (wm * 16 + (lane & 15)) * 136 +
                                   kk * 16 + (lane >> 4) * 8);
            LDSM_X4(pah, ad);
            ad = smem_u32(Pl + (wm * 16 + (lane & 15)) * 136 +
                          kk * 16 + (lane >> 4) * 8);
            LDSM_X4(pal, ad);
#pragma unroll
            for (int t = 0; t < 2; t++) {
                ad = smem_u32(VBh + (kk * 16 + (lane & 15)) * 72 +
                              wn * 16 + t * 8);
                LDSM_X2T(bvh[t], ad);
                ad = smem_u32(VBl + (kk * 16 + (lane & 15)) * 72 +
                              wn * 16 + t * 8);
                LDSM_X2T(bvl[t], ad);
            }
#pragma unroll
            for (int t = 0; t < 2; t++) MMA_STEP(pah, bvh[t], cacc[t]);
#pragma unroll
            for (int t = 0; t < 2; t++) MMA_STEP(pal, bvh[t], cacc[t]);
#pragma unroll
            for (int t = 0; t < 2; t++) MMA_STEP(pah, bvl[t], cacc[t]);
        }
    }

    // ---- write context as bf16 split 2D [B*L][1024] ----
    {
        int h_ = bh & 15;
        int row = q0 + wm * 16 + (lane >> 2);
#pragma unroll
        for (int t = 0; t < 2; t++) {
            int d = wn * 16 + t * 8 + 2 * (lane & 3);
#pragma unroll
            for (int hrow = 0; hrow < 2; hrow++) {
                float v0 = cacc[t][hrow * 2 + 0];
                float v1 = cacc[t][hrow * 2 + 1];
                __nv_bfloat16 h0 = __float2bfloat16(v0);
                __nv_bfloat16 h1 = __float2bfloat16(v1);
                size_t off = ((size_t)(b_ * L) + row + hrow * 8) * DM + h_ * 64 + d;
                *(__nv_bfloat162*)(g_Ch + off) = __nv_bfloat162(h0, h1);
                *(__nv_bfloat162*)(g_Cl + off) = __nv_bfloat162(
                    __float2bfloat16(v0 - __bfloat162float(h0)),
                    __float2bfloat16(v1 - __bfloat162float(h1)));
            }
        }
    }
}

// ---------------- layernorm --------------------------------------------------
__global__ __launch_bounds__(256) void ln_kernel(
    const float* __restrict__ gamma, const float* __restrict__ beta,
    float* __restrict__ out)
{
    __shared__ float red[18];
    const int r = blockIdx.x, tid = threadIdx.x;
    const float4* x4 = (const float4*)(g_preln + (size_t)r * DM);
    float4 v = x4[tid];

    float s = v.x + v.y + v.z + v.w;
#pragma unroll
    for (int off = 16; off; off >>= 1) s += __shfl_xor_sync(0xffffffffu, s, off);
    if ((tid & 31) == 0) red[tid >> 5] = s;
    __syncthreads();
    if (tid == 0) {
        float t = 0.f;
        for (int i = 0; i < 8; i++) t += red[i];
        red[16] = t * (1.f / 1024.f);
    }
    __syncthreads();
    float mean = red[16];

    float dx = v.x - mean, dy = v.y - mean, dz = v.z - mean, dw = v.w - mean;
    float ss = dx * dx + dy * dy + dz * dz + dw * dw;
#pragma unroll
    for (int off = 16; off; off >>= 1) ss += __shfl_xor_sync(0xffffffffu, ss, off);
    if ((tid & 31) == 0) red[8 + (tid >> 5)] = ss;
    __syncthreads();
    if (tid == 0) {
        float t = 0.f;
        for (int i = 0; i < 8; i++) t += red[8 + i];
        red[17] = rsqrtf(t * (1.f / 1024.f) + 1e-6f);
    }
    __syncthreads();
    float rs = red[17];

    float4 g = ((const float4*)gamma)[tid];
    float4 bb = ((const float4*)beta)[tid];
    float4 o;
    o.x = dx * rs * g.x + bb.x;
    o.y = dy * rs * g.y + bb.y;
    o.z = dz * rs * g.z + bb.z;
    o.w = dw * rs * g.w + bb.w;

    float* op = out ? (out + (size_t)r * DM) : (g_preln + (size_t)r * DM);
    ((float4*)op)[tid] = o;
}

// ---------------- launch -----------------------------------------------------
extern "C" void kernel_launch(void* const* d_in, const int* in_sizes, int n_in,
                              void* d_out, int out_size)
{
    const float* X     = (const float*)d_in[0];
    const void*  mask  = d_in[1];
    const float* Wq    = (const float*)d_in[2];
    const float* Wk    = (const float*)d_in[3];
    const float* Wv    = (const float*)d_in[4];
    const float* Wo    = (const float*)d_in[5];
    const float* gamma = (const float*)d_in[6];
    const float* beta  = (const float*)d_in[7];

    const long long LNN = (long long)B * L * DM;
    const long long ATT = (long long)BH * L * L;

    float* out_ln = nullptr;
    float* out_attn = nullptr;
    long long os = (long long)out_size;
    if (os >= LNN + ATT) {
        out_ln = (float*)d_out;
        out_attn = (float*)d_out + LNN;
    } else if (os == ATT) {
        out_attn = (float*)d_out;
    } else {
        out_ln = (float*)d_out;
    }

    detect_mask_kernel<<<1, 256>>>((const unsigned int*)mask);

    __nv_bfloat16 *Xh, *Xl, *Wh0, *Wl0;
    cudaGetSymbolAddress((void**)&Xh, g_Xh);
    cudaGetSymbolAddress((void**)&Xl, g_Xl);
    cudaGetSymbolAddress((void**)&Wh0, g_Wh);
    cudaGetSymbolAddress((void**)&Wl0, g_Wl);

    int nX4 = (B * L * DM) / 4;
    int nW4 = (DM * DM) / 4;
    cvt_split_kernel<<<(nX4 + 255) / 256, 256>>>((const float4*)X, Xh, Xl, nX4);
    cvt_split_kernel<<<(nW4 + 255) / 256, 256>>>((const float4*)Wq,
        Wh0 + 0 * (size_t)DM * DM, Wl0 + 0 * (size_t)DM * DM, nW4);
    cvt_split_kernel<<<(nW4 + 255) / 256, 256>>>((const float4*)Wk,
        Wh0 + 1 * (size_t)DM * DM, Wl0 + 1 * (size_t)DM * DM, nW4);
    cvt_split_kernel<<<(nW4 + 255) / 256, 256>>>((const float4*)Wv,
        Wh0 + 2 * (size_t)DM * DM, Wl0 + 2 * (size_t)DM * DM, nW4);
    cvt_split_kernel<<<(nW4 + 255) / 256, 256>>>((const float4*)Wo,
        Wh0 + 3 * (size_t)DM * DM, Wl0 + 3 * (size_t)DM * DM, nW4);

    qkv_mma_kernel<<<dim3(8, 64, 3), 256>>>();

    cudaFuncSetAttribute(attn_mma_kernel,
                         cudaFuncAttributeMaxDynamicSharedMemorySize, ATTN_SMEM);
    attn_mma_kernel<<<dim3(L / 32, BH), 256, ATTN_SMEM>>>(mask, out_attn);

    oproj_mma_kernel<<<dim3(8, 64), 256>>>(X);
    ln_kernel<<<B * L, 256>>>(gamma, beta, out_ln);
}